// round 8
// baseline (speedup 1.0000x reference)
#include <cuda_runtime.h>
#include <cuda_fp16.h>
#include <math.h>
#include <stdint.h>

#define NE 8
#define DIM 1024
#define IDIM 2048
#define NTOK 4096
#define ESTRIDE 4096

// ---------------- device scratch ----------------
__device__ int   g_count[NE];
__device__ int   g_rows[NE * ESTRIDE];
__device__ float g_w[NE * ESTRIDE];
__device__ __half g_xh[NTOK * DIM];
__device__ __half g_wg[NE * IDIM * DIM];   // [e][i][d] K-major (K=d)
__device__ __half g_wu[NE * IDIM * DIM];
__device__ __half g_wd[NE * DIM * IDIM];   // [e][d][i] K-major (K=i)
__device__ __half g_hh[(size_t)NE * ESTRIDE * IDIM];

// ---------------- helpers ----------------
__device__ __forceinline__ uint32_t smem_u32(const void* p) {
    uint32_t a;
    asm("{ .reg .u64 t; cvta.to.shared.u64 t, %1; cvt.u32.u64 %0, t; }"
        : "=r"(a) : "l"(p));
    return a;
}

#define LDSM4(r0, r1, r2, r3, addr)                                          \
    asm volatile("ldmatrix.sync.aligned.m8n8.x4.shared.b16 {%0,%1,%2,%3}, [%4];" \
                 : "=r"(r0), "=r"(r1), "=r"(r2), "=r"(r3) : "r"(addr))

#define MMA16816(c, a, b)                                                    \
    asm volatile("mma.sync.aligned.m16n8k16.row.col.f32.f16.f16.f32 "        \
                 "{%0,%1,%2,%3},{%4,%5,%6,%7},{%8,%9},{%0,%1,%2,%3};"        \
                 : "+f"((c)[0]), "+f"((c)[1]), "+f"((c)[2]), "+f"((c)[3])    \
                 : "r"((a)[0]), "r"((a)[1]), "r"((a)[2]), "r"((a)[3]),       \
                   "r"((b)[0]), "r"((b)[1]))

#define CPA16(dst, src, sz)                                                  \
    asm volatile("cp.async.cg.shared.global [%0], [%1], 16, %2;"             \
                 :: "r"(dst), "l"(src), "r"(sz) : "memory")
#define CP_COMMIT() asm volatile("cp.async.commit_group;" ::: "memory")
#define CP_WAIT(n)  asm volatile("cp.async.wait_group %0;" ::"n"(n) : "memory")

// ---------------- init ----------------
__global__ void init_kernel(float* __restrict__ out, int n) {
    int i = blockIdx.x * blockDim.x + threadIdx.x;
    if (i < NE) g_count[i] = 0;
    for (int j = i; j < n; j += gridDim.x * blockDim.x) out[j] = 0.0f;
}

// ---------------- x -> fp16 ----------------
__global__ void conv_x_kernel(const float* __restrict__ x) {
    int i = blockIdx.x * blockDim.x + threadIdx.x;
    const int N4 = NTOK * DIM / 4;
    for (int j = i; j < N4; j += gridDim.x * blockDim.x) {
        float4 v = reinterpret_cast<const float4*>(x)[j];
        __half hv[4] = {__float2half_rn(v.x), __float2half_rn(v.y),
                        __float2half_rn(v.z), __float2half_rn(v.w)};
        reinterpret_cast<uint2*>(g_xh)[j] = *reinterpret_cast<uint2*>(hv);
    }
}

// -------- transpose: in [E][R][C] fp32 -> out [E][C][R] fp16 --------
__global__ void transpose_half_kernel(const float* __restrict__ in,
                                      __half* __restrict__ oh,
                                      int R, int C) {
    __shared__ float t[32][65];   // [c][r]
    int e = blockIdx.z;
    const float* ine = in + (size_t)e * R * C;
    int c0 = blockIdx.x * 32, r0 = blockIdx.y * 64;
    int tid = threadIdx.x;
    int cx = tid & 31, ry = tid >> 5;
#pragma unroll
    for (int i = 0; i < 64; i += 8)
        t[cx][ry + i] = ine[(size_t)(r0 + ry + i) * C + c0 + cx];
    __syncthreads();
    __half* ohe = oh + (size_t)e * R * C;
    int rx = tid & 63, cy = tid >> 6;
#pragma unroll
    for (int j = 0; j < 32; j += 4)
        ohe[(size_t)(c0 + cy + j) * R + r0 + rx] = __float2half_rn(t[cy + j][rx]);
}

// ---------------- routing: one warp per token ----------------
__global__ void route_kernel(const float* __restrict__ x,
                             const float* __restrict__ Wc,
                             const float* __restrict__ bc) {
    int gwarp = (blockIdx.x * blockDim.x + threadIdx.x) >> 5;
    int lane = threadIdx.x & 31;
    if (gwarp >= NTOK) return;
    const float* xr = x + (size_t)gwarp * DIM;
    float acc[NE];
#pragma unroll
    for (int e = 0; e < NE; e++) acc[e] = 0.0f;
    for (int d = lane; d < DIM; d += 32) {
        float xv = xr[d];
#pragma unroll
        for (int e = 0; e < NE; e++) acc[e] += xv * Wc[e * DIM + d];
    }
#pragma unroll
    for (int e = 0; e < NE; e++)
#pragma unroll
        for (int off = 16; off > 0; off >>= 1)
            acc[e] += __shfl_xor_sync(0xffffffffu, acc[e], off);
    if (lane == 0) {
        float conf[NE];
#pragma unroll
        for (int e = 0; e < NE; e++)
            conf[e] = 1.0f / (1.0f + expf(-(acc[e] + bc[e])));
        int i0 = 0;
#pragma unroll
        for (int e = 1; e < NE; e++) if (conf[e] > conf[i0]) i0 = e;
        int i1 = -1;
#pragma unroll
        for (int e = 0; e < NE; e++) {
            if (e == i0) continue;
            if (i1 < 0 || conf[e] > conf[i1]) i1 = e;
        }
        float v0 = conf[i0], v1 = conf[i1];
        float w0 = 1.0f / (1.0f + expf(v1 - v0));
        float w1 = 1.0f / (1.0f + expf(v0 - v1));
        int p0 = atomicAdd(&g_count[i0], 1);
        g_rows[i0 * ESTRIDE + p0] = gwarp;
        g_w[i0 * ESTRIDE + p0] = w0;
        int p1 = atomicAdd(&g_count[i1], 1);
        g_rows[i1 * ESTRIDE + p1] = gwarp;
        g_w[i1 * ESTRIDE + p1] = w1;
    }
}

// =======================================================================
// Tiling: Kc=64, smem rows 144B (64 halves + 8 pad), conflict-free ldmatrix.
// M-tile 256 (halves redundant weight traffic); warp tiles 64-wide in M.
// =======================================================================
#define RBYTES  144

// -------- up kernel smem stage layout (bytes): A 256 rows, Bg/Bu 64 rows --------
#define U_A   0                     // 256*144 = 36864
#define U_BG  36864                 // 64*144 = 9216
#define U_BU  46080
#define U_STAGE 55296
#define U_SMEM (2 * U_STAGE)        // 110592

// -------- down kernel smem stage layout: A 256 rows, B 128 rows --------
#define D_A   0                     // 256*144 = 36864
#define D_B   36864                 // 128*144 = 18432
#define D_STAGE 55296
#define D_SMEM (2 * D_STAGE)        // 110592

// =======================================================================
// up: g = X*Wg^T, u = X*Wu^T; h = silu(g)*u -> fp16
// CTA 256(M) x 64(N of IDIM), Kc=64; 8 warps grid 4(m)x2(n), warp 64x32 (x2 outputs)
// =======================================================================
__global__ __launch_bounds__(256, 1)
void up_mma_kernel() {
    extern __shared__ char dsm[];
    __shared__ int stok[256];

    int e = blockIdx.z, m0 = blockIdx.x * 256, n0 = blockIdx.y * 64;
    int ne = g_count[e];
    if (m0 >= ne) return;
    int tid = threadIdx.x, wid = tid >> 5, l = tid & 31;
    stok[tid] = (m0 + tid < ne) ? g_rows[e * ESTRIDE + m0 + tid] : -1;
    __syncthreads();

    int wm = wid & 3, wn = wid >> 2;   // 4 x 2

    const __half* WG = g_wg + (size_t)e * IDIM * DIM;
    const __half* WU = g_wu + (size_t)e * IDIM * DIM;

    uint32_t sb = smem_u32(dsm);

    int lrow = tid >> 3, lch = tid & 7;   // 32 rows x 8 chunks per 256 threads

    int lar = (l & 7) + 8 * ((l >> 3) & 1);
    int lac = 8 * (l >> 4);
    int lbr = (l & 7) + 8 * (l >> 4);
    int lbc = 8 * ((l >> 3) & 1);

    float cg[4][4][4], cu[4][4][4];
#pragma unroll
    for (int i = 0; i < 4; i++)
#pragma unroll
        for (int j = 0; j < 4; j++)
#pragma unroll
            for (int q = 0; q < 4; q++) { cg[i][j][q] = 0.f; cu[i][j][q] = 0.f; }

    const int NK = DIM / 64;

    auto load_stage = [&](int kc, int s) {
        uint32_t st = sb + s * U_STAGE;
        int k0 = kc * 64;
        // A: 256 rows x 8 chunks = 2048 ops, 8 per thread
#pragma unroll
        for (int it = 0; it < 8; it++) {
            int row = lrow + it * 32;
            int tok = stok[row];
            uint32_t sz = (tok >= 0) ? 16u : 0u;
            size_t go = (tok >= 0) ? ((size_t)tok * DIM + k0 + lch * 8) : 0;
            CPA16(st + U_A + row * RBYTES + lch * 16, g_xh + go, sz);
        }
        // Bg/Bu: 64 rows x 8 chunks = 512 each, 2 per thread each
#pragma unroll
        for (int it = 0; it < 2; it++) {
            int row = lrow + it * 32;
            size_t go = (size_t)(n0 + row) * DIM + k0 + lch * 8;
            uint32_t so = row * RBYTES + lch * 16;
            CPA16(st + U_BG + so, WG + go, 16u);
            CPA16(st + U_BU + so, WU + go, 16u);
        }
        CP_COMMIT();
    };

    load_stage(0, 0);

    for (int kc = 0; kc < NK; kc++) {
        if (kc + 1 < NK) { load_stage(kc + 1, (kc + 1) & 1); CP_WAIT(1); }
        else             { CP_WAIT(0); }
        __syncthreads();

        uint32_t st = sb + (kc & 1) * U_STAGE;
#pragma unroll
        for (int ks = 0; ks < 4; ks++) {
            int kkb = ks * 32;
            uint32_t ah[4][4];
#pragma unroll
            for (int mf = 0; mf < 4; mf++) {
                uint32_t off = (uint32_t)((wm * 64 + mf * 16 + lar) * RBYTES + kkb + lac * 2);
                LDSM4(ah[mf][0], ah[mf][1], ah[mf][2], ah[mf][3], st + U_A + off);
            }
#pragma unroll
            for (int p = 0; p < 2; p++) {
                uint32_t off = (uint32_t)((wn * 32 + p * 16 + lbr) * RBYTES + kkb + lbc * 2);
                uint32_t bg[2][2], bu[2][2];
                LDSM4(bg[0][0], bg[0][1], bg[1][0], bg[1][1], st + U_BG + off);
                LDSM4(bu[0][0], bu[0][1], bu[1][0], bu[1][1], st + U_BU + off);
#pragma unroll
                for (int mf = 0; mf < 4; mf++)
#pragma unroll
                    for (int q = 0; q < 2; q++) {
                        int nf = 2 * p + q;
                        MMA16816(cg[mf][nf], ah[mf], bg[q]);
                        MMA16816(cu[mf][nf], ah[mf], bu[q]);
                    }
            }
        }
        __syncthreads();
    }

    // epilogue: h = silu(g) * u -> fp16
    __half* hh = g_hh + (size_t)e * ESTRIDE * IDIM;
#pragma unroll
    for (int mf = 0; mf < 4; mf++) {
        int r_lo = m0 + wm * 64 + mf * 16 + (l >> 2);
#pragma unroll
        for (int nf = 0; nf < 4; nf++) {
            int col = n0 + wn * 32 + nf * 8 + 2 * (l & 3);
#pragma unroll
            for (int half_ = 0; half_ < 2; half_++) {
                int r = r_lo + half_ * 8;
                if (r >= ne) continue;
                float gv0 = cg[mf][nf][half_ * 2 + 0], gv1 = cg[mf][nf][half_ * 2 + 1];
                float uv0 = cu[mf][nf][half_ * 2 + 0], uv1 = cu[mf][nf][half_ * 2 + 1];
                float h0 = uv0 * gv0 / (1.0f + expf(-gv0));
                float h1 = uv1 * gv1 / (1.0f + expf(-gv1));
                __half ph[2] = {__float2half_rn(h0), __float2half_rn(h1)};
                *reinterpret_cast<uint32_t*>(hh + (size_t)r * IDIM + col) =
                    *reinterpret_cast<uint32_t*>(ph);
            }
        }
    }
}

// =======================================================================
// down: Y = H*Wd^T; out[token] += w * Y
// CTA 256(M) x 128(N of DIM), Kc=64 over K=2048; 8 warps 4(m)x2(n), warp 64x64
// =======================================================================
__global__ __launch_bounds__(256, 1)
void down_mma_kernel(float* __restrict__ out) {
    extern __shared__ char dsm[];

    int e = blockIdx.z, m0 = blockIdx.x * 256, n0 = blockIdx.y * 128;
    int ne = g_count[e];
    if (m0 >= ne) return;
    int tid = threadIdx.x, wid = tid >> 5, l = tid & 31;
    int wm = wid & 3, wn = wid >> 2;   // 4 x 2

    const __half* AH = g_hh + (size_t)e * ESTRIDE * IDIM;
    const __half* B  = g_wd + (size_t)e * DIM * IDIM;

    uint32_t sb = smem_u32(dsm);

    int lrow = tid >> 3, lch = tid & 7;

    int lar = (l & 7) + 8 * ((l >> 3) & 1);
    int lac = 8 * (l >> 4);
    int lbr = (l & 7) + 8 * (l >> 4);
    int lbc = 8 * ((l >> 3) & 1);

    float c[4][8][4];
#pragma unroll
    for (int i = 0; i < 4; i++)
#pragma unroll
        for (int j = 0; j < 8; j++)
#pragma unroll
            for (int q = 0; q < 4; q++) c[i][j][q] = 0.f;

    const int NK = IDIM / 64;

    auto load_stage = [&](int kc, int s) {
        uint32_t st = sb + s * D_STAGE;
        int k0 = kc * 64;
        // A: 256 rows, 8 per thread (zero-fill rows past ne)
#pragma unroll
        for (int it = 0; it < 8; it++) {
            int row = lrow + it * 32;
            uint32_t sz = (m0 + row < ne) ? 16u : 0u;
            size_t ga = (m0 + row < ne) ? ((size_t)(m0 + row) * IDIM + k0 + lch * 8) : 0;
            CPA16(st + D_A + row * RBYTES + lch * 16, AH + ga, sz);
        }
        // B: 128 rows, 4 per thread
#pragma unroll
        for (int it = 0; it < 4; it++) {
            int row = lrow + it * 32;
            size_t gb = (size_t)(n0 + row) * IDIM + k0 + lch * 8;
            CPA16(st + D_B + row * RBYTES + lch * 16, B + gb, 16u);
        }
        CP_COMMIT();
    };

    load_stage(0, 0);

    for (int kc = 0; kc < NK; kc++) {
        if (kc + 1 < NK) { load_stage(kc + 1, (kc + 1) & 1); CP_WAIT(1); }
        else             { CP_WAIT(0); }
        __syncthreads();

        uint32_t st = sb + (kc & 1) * D_STAGE;
#pragma unroll
        for (int ks = 0; ks < 4; ks++) {
            int kkb = ks * 32;
            uint32_t ah[4][4];
#pragma unroll
            for (int mf = 0; mf < 4; mf++) {
                uint32_t off = (uint32_t)((wm * 64 + mf * 16 + lar) * RBYTES + kkb + lac * 2);
                LDSM4(ah[mf][0], ah[mf][1], ah[mf][2], ah[mf][3], st + D_A + off);
            }
#pragma unroll
            for (int p = 0; p < 4; p++) {
                uint32_t off = (uint32_t)((wn * 64 + p * 16 + lbr) * RBYTES + kkb + lbc * 2);
                uint32_t bh[2][2];
                LDSM4(bh[0][0], bh[0][1], bh[1][0], bh[1][1], st + D_B + off);
#pragma unroll
                for (int mf = 0; mf < 4; mf++)
#pragma unroll
                    for (int q = 0; q < 2; q++)
                        MMA16816(c[mf][2 * p + q], ah[mf], bh[q]);
            }
        }
        __syncthreads();
    }

    // epilogue: weighted atomic combine
#pragma unroll
    for (int mf = 0; mf < 4; mf++) {
        int r_lo = m0 + wm * 64 + mf * 16 + (l >> 2);
#pragma unroll
        for (int half_ = 0; half_ < 2; half_++) {
            int r = r_lo + half_ * 8;
            if (r >= ne) continue;
            int   t = g_rows[e * ESTRIDE + r];
            float w = g_w[e * ESTRIDE + r];
            float* op = out + (size_t)t * DIM;
#pragma unroll
            for (int nf = 0; nf < 8; nf++) {
                int col = n0 + wn * 64 + nf * 8 + 2 * (l & 3);
                atomicAdd(op + col,     w * c[mf][nf][half_ * 2 + 0]);
                atomicAdd(op + col + 1, w * c[mf][nf][half_ * 2 + 1]);
            }
        }
    }
}

// ---------------- launcher ----------------
extern "C" void kernel_launch(void* const* d_in, const int* in_sizes, int n_in,
                              void* d_out, int out_size) {
    const float* hs = (const float*)d_in[0];
    const float* Wc = (const float*)d_in[1];
    const float* bc = (const float*)d_in[2];
    const float* Wg = (const float*)d_in[3];
    const float* Wu = (const float*)d_in[4];
    const float* Wd = (const float*)d_in[5];
    float* out = (float*)d_out;

    cudaFuncSetAttribute(up_mma_kernel, cudaFuncAttributeMaxDynamicSharedMemorySize, U_SMEM);
    cudaFuncSetAttribute(down_mma_kernel, cudaFuncAttributeMaxDynamicSharedMemorySize, D_SMEM);

    init_kernel<<<1024, 256>>>(out, out_size);
    conv_x_kernel<<<2048, 256>>>(hs);

    __half *wg, *wu, *wd;
    cudaGetSymbolAddress((void**)&wg, g_wg);
    cudaGetSymbolAddress((void**)&wu, g_wu);
    cudaGetSymbolAddress((void**)&wd, g_wd);

    transpose_half_kernel<<<dim3(IDIM / 32, DIM / 64, NE), 256>>>(Wg, wg, DIM, IDIM);
    transpose_half_kernel<<<dim3(IDIM / 32, DIM / 64, NE), 256>>>(Wu, wu, DIM, IDIM);
    transpose_half_kernel<<<dim3(DIM / 32, IDIM / 64, NE), 256>>>(Wd, wd, IDIM, DIM);

    route_kernel<<<(NTOK * 32) / 256, 256>>>(hs, Wc, bc);

    up_mma_kernel<<<dim3(NTOK / 256, IDIM / 64, NE), 256, U_SMEM>>>();
    down_mma_kernel<<<dim3(NTOK / 256, DIM / 128, NE), 256, D_SMEM>>>(out);
}

// round 9
// speedup vs baseline: 1.1410x; 1.1410x over previous
#include <cuda_runtime.h>
#include <cuda_fp16.h>
#include <math.h>
#include <stdint.h>

#define NE 8
#define DIM 1024
#define IDIM 2048
#define NTOK 4096
#define ESTRIDE 4096

// ---------------- device scratch ----------------
__device__ int   g_count[NE];
__device__ int   g_rows[NE * ESTRIDE];
__device__ float g_w[NE * ESTRIDE];
__device__ __half g_xh[NTOK * DIM];
__device__ __half g_wg[NE * IDIM * DIM];   // [e][i][d] K-major (K=d)
__device__ __half g_wu[NE * IDIM * DIM];
__device__ __half g_wd[NE * DIM * IDIM];   // [e][d][i] K-major (K=i)
__device__ __half g_hh[(size_t)NE * ESTRIDE * IDIM];

// ---------------- helpers ----------------
__device__ __forceinline__ uint32_t smem_u32(const void* p) {
    uint32_t a;
    asm("{ .reg .u64 t; cvta.to.shared.u64 t, %1; cvt.u32.u64 %0, t; }"
        : "=r"(a) : "l"(p));
    return a;
}

#define LDSM4(r0, r1, r2, r3, addr)                                          \
    asm volatile("ldmatrix.sync.aligned.m8n8.x4.shared.b16 {%0,%1,%2,%3}, [%4];" \
                 : "=r"(r0), "=r"(r1), "=r"(r2), "=r"(r3) : "r"(addr))

#define MMA16816(c, a, b)                                                    \
    asm volatile("mma.sync.aligned.m16n8k16.row.col.f32.f16.f16.f32 "        \
                 "{%0,%1,%2,%3},{%4,%5,%6,%7},{%8,%9},{%0,%1,%2,%3};"        \
                 : "+f"((c)[0]), "+f"((c)[1]), "+f"((c)[2]), "+f"((c)[3])    \
                 : "r"((a)[0]), "r"((a)[1]), "r"((a)[2]), "r"((a)[3]),       \
                   "r"((b)[0]), "r"((b)[1]))

#define CPA16(dst, src, sz)                                                  \
    asm volatile("cp.async.cg.shared.global [%0], [%1], 16, %2;"             \
                 :: "r"(dst), "l"(src), "r"(sz) : "memory")
#define CP_COMMIT() asm volatile("cp.async.commit_group;" ::: "memory")
#define CP_WAIT(n)  asm volatile("cp.async.wait_group %0;" ::"n"(n) : "memory")

// =======================================================================
// fused prologue: [transpose wg | transpose wu | transpose wd | conv_x |
//                  route | zero out] partitioned by blockIdx.x
// =======================================================================
#define NB_T    8192                 // blocks per transpose
#define NB_CONV 1024
#define NB_ROUTE 512
#define NB_ZERO 512
#define NB_TOTAL (3 * NB_T + NB_CONV + NB_ROUTE + NB_ZERO)

__device__ __forceinline__ void do_transpose(const float* in, __half* oh,
                                             int R, int C, int t, int tid,
                                             float (*sm)[65]) {
    int tilesX = C / 32, tilesY = R / 64;
    int per_e = tilesX * tilesY;
    int e = t / per_e, rem = t - e * per_e;
    int bx = rem % tilesX, by = rem / tilesX;
    const float* ine = in + (size_t)e * R * C;
    int c0 = bx * 32, r0 = by * 64;
    int cx = tid & 31, ry = tid >> 5;
#pragma unroll
    for (int i = 0; i < 64; i += 8)
        sm[cx][ry + i] = ine[(size_t)(r0 + ry + i) * C + c0 + cx];
    __syncthreads();
    __half* ohe = oh + (size_t)e * R * C;
    int rx = tid & 63, cy = tid >> 6;
#pragma unroll
    for (int j = 0; j < 32; j += 4)
        ohe[(size_t)(c0 + cy + j) * R + r0 + rx] = __float2half_rn(sm[cy + j][rx]);
}

__device__ __forceinline__ void do_route(const float* x, const float* Wc,
                                         const float* bc, int rb, int tid) {
    int gwarp = (rb * 256 + tid) >> 5;
    int lane = tid & 31;
    const float* xr = x + (size_t)gwarp * DIM;
    float acc[NE];
#pragma unroll
    for (int e = 0; e < NE; e++) acc[e] = 0.0f;
    for (int d = lane; d < DIM; d += 32) {
        float xv = xr[d];
#pragma unroll
        for (int e = 0; e < NE; e++) acc[e] += xv * Wc[e * DIM + d];
    }
#pragma unroll
    for (int e = 0; e < NE; e++)
#pragma unroll
        for (int off = 16; off > 0; off >>= 1)
            acc[e] += __shfl_xor_sync(0xffffffffu, acc[e], off);
    if (lane == 0) {
        float conf[NE];
#pragma unroll
        for (int e = 0; e < NE; e++)
            conf[e] = 1.0f / (1.0f + expf(-(acc[e] + bc[e])));
        int i0 = 0;
#pragma unroll
        for (int e = 1; e < NE; e++) if (conf[e] > conf[i0]) i0 = e;
        int i1 = -1;
#pragma unroll
        for (int e = 0; e < NE; e++) {
            if (e == i0) continue;
            if (i1 < 0 || conf[e] > conf[i1]) i1 = e;
        }
        float v0 = conf[i0], v1 = conf[i1];
        float w0 = 1.0f / (1.0f + expf(v1 - v0));
        float w1 = 1.0f / (1.0f + expf(v0 - v1));
        int p0 = atomicAdd(&g_count[i0], 1);
        g_rows[i0 * ESTRIDE + p0] = gwarp;
        g_w[i0 * ESTRIDE + p0] = w0;
        int p1 = atomicAdd(&g_count[i1], 1);
        g_rows[i1 * ESTRIDE + p1] = gwarp;
        g_w[i1 * ESTRIDE + p1] = w1;
    }
}

__global__ __launch_bounds__(256)
void prologue_kernel(const float* __restrict__ hs,
                     const float* __restrict__ Wc,
                     const float* __restrict__ bc,
                     const float* __restrict__ Wg,
                     const float* __restrict__ Wu,
                     const float* __restrict__ Wd,
                     float* __restrict__ out, int out_n) {
    __shared__ float sm[32][65];
    int b = blockIdx.x, tid = threadIdx.x;
    if (b < NB_T) {
        do_transpose(Wg, g_wg, DIM, IDIM, b, tid, sm);            // [E][D][I]->[E][I][D]
    } else if (b < 2 * NB_T) {
        do_transpose(Wu, g_wu, DIM, IDIM, b - NB_T, tid, sm);
    } else if (b < 3 * NB_T) {
        do_transpose(Wd, g_wd, IDIM, DIM, b - 2 * NB_T, tid, sm); // [E][I][D]->[E][D][I]
    } else if (b < 3 * NB_T + NB_CONV) {
        int cb = b - 3 * NB_T;
        const int N4 = NTOK * DIM / 4;
        for (int j = cb * 256 + tid; j < N4; j += NB_CONV * 256) {
            float4 v = reinterpret_cast<const float4*>(hs)[j];
            __half hv[4] = {__float2half_rn(v.x), __float2half_rn(v.y),
                            __float2half_rn(v.z), __float2half_rn(v.w)};
            reinterpret_cast<uint2*>(g_xh)[j] = *reinterpret_cast<uint2*>(hv);
        }
    } else if (b < 3 * NB_T + NB_CONV + NB_ROUTE) {
        do_route(hs, Wc, bc, b - 3 * NB_T - NB_CONV, tid);
    } else {
        int zb = b - 3 * NB_T - NB_CONV - NB_ROUTE;
        int n4 = out_n / 4;
        float4 z = make_float4(0.f, 0.f, 0.f, 0.f);
        for (int j = zb * 256 + tid; j < n4; j += NB_ZERO * 256)
            reinterpret_cast<float4*>(out)[j] = z;
    }
}

// =======================================================================
// Tiling: Kc=64, rows padded to 144B (64 halves + 8 pad) — conflict-free.
// (R7 configuration: M=128, 2 CTAs/SM)
// =======================================================================
#define RBYTES  144

#define U_A   0                 // 128*144 = 18432
#define U_BG  18432             // 64*144 = 9216
#define U_BU  27648
#define U_STAGE 36864
#define U_SMEM (2 * U_STAGE)

#define D_A   0                 // 128*144
#define D_B   18432             // 128*144
#define D_STAGE 36864
#define D_SMEM (2 * D_STAGE)

// =======================================================================
// up: g = X*Wg^T, u = X*Wu^T (fp16, fp32 accum); h = silu(g)*u -> fp16
// CTA 128(M) x 64(N of IDIM), Kc=64; cp.async depth-2
// =======================================================================
__global__ __launch_bounds__(256)
void up_mma_kernel() {
    extern __shared__ char dsm[];
    __shared__ int stok[128];

    int e = blockIdx.z, m0 = blockIdx.x * 128, n0 = blockIdx.y * 64;
    int ne = g_count[e];
    if (m0 >= ne) return;
    int tid = threadIdx.x, wid = tid >> 5, l = tid & 31;
    if (tid < 128) stok[tid] = (m0 + tid < ne) ? g_rows[e * ESTRIDE + m0 + tid] : -1;
    __syncthreads();

    int wm = wid & 3, wn = wid >> 2;

    const __half* WG = g_wg + (size_t)e * IDIM * DIM;
    const __half* WU = g_wu + (size_t)e * IDIM * DIM;

    uint32_t sb = smem_u32(dsm);

    int lrow = tid >> 3, lch = tid & 7;

    int lar = (l & 7) + 8 * ((l >> 3) & 1);
    int lac = 8 * (l >> 4);
    int lbr = (l & 7) + 8 * (l >> 4);
    int lbc = 8 * ((l >> 3) & 1);

    float cg[2][4][4], cu[2][4][4];
#pragma unroll
    for (int i = 0; i < 2; i++)
#pragma unroll
        for (int j = 0; j < 4; j++)
#pragma unroll
            for (int q = 0; q < 4; q++) { cg[i][j][q] = 0.f; cu[i][j][q] = 0.f; }

    const int NK = DIM / 64;

    auto load_stage = [&](int kc, int s) {
        uint32_t st = sb + s * U_STAGE;
        int k0 = kc * 64;
#pragma unroll
        for (int it = 0; it < 4; it++) {
            int row = lrow + it * 32;
            int tok = stok[row];
            uint32_t sz = (tok >= 0) ? 16u : 0u;
            size_t go = (tok >= 0) ? ((size_t)tok * DIM + k0 + lch * 8) : 0;
            CPA16(st + U_A + row * RBYTES + lch * 16, g_xh + go, sz);
        }
#pragma unroll
        for (int it = 0; it < 2; it++) {
            int row = lrow + it * 32;
            size_t go = (size_t)(n0 + row) * DIM + k0 + lch * 8;
            uint32_t so = row * RBYTES + lch * 16;
            CPA16(st + U_BG + so, WG + go, 16u);
            CPA16(st + U_BU + so, WU + go, 16u);
        }
        CP_COMMIT();
    };

    load_stage(0, 0);

    for (int kc = 0; kc < NK; kc++) {
        if (kc + 1 < NK) { load_stage(kc + 1, (kc + 1) & 1); CP_WAIT(1); }
        else             { CP_WAIT(0); }
        __syncthreads();

        uint32_t st = sb + (kc & 1) * U_STAGE;
#pragma unroll
        for (int ks = 0; ks < 4; ks++) {
            int kkb = ks * 32;
            uint32_t ah[2][4];
#pragma unroll
            for (int mf = 0; mf < 2; mf++) {
                uint32_t off = (uint32_t)((wm * 32 + mf * 16 + lar) * RBYTES + kkb + lac * 2);
                LDSM4(ah[mf][0], ah[mf][1], ah[mf][2], ah[mf][3], st + U_A + off);
            }
#pragma unroll
            for (int p = 0; p < 2; p++) {
                uint32_t off = (uint32_t)((wn * 32 + p * 16 + lbr) * RBYTES + kkb + lbc * 2);
                uint32_t bg[2][2], bu[2][2];
                LDSM4(bg[0][0], bg[0][1], bg[1][0], bg[1][1], st + U_BG + off);
                LDSM4(bu[0][0], bu[0][1], bu[1][0], bu[1][1], st + U_BU + off);
#pragma unroll
                for (int mf = 0; mf < 2; mf++)
#pragma unroll
                    for (int q = 0; q < 2; q++) {
                        int nf = 2 * p + q;
                        MMA16816(cg[mf][nf], ah[mf], bg[q]);
                        MMA16816(cu[mf][nf], ah[mf], bu[q]);
                    }
            }
        }
        __syncthreads();
    }

    __half* hh = g_hh + (size_t)e * ESTRIDE * IDIM;
#pragma unroll
    for (int mf = 0; mf < 2; mf++) {
        int r_lo = m0 + wm * 32 + mf * 16 + (l >> 2);
#pragma unroll
        for (int nf = 0; nf < 4; nf++) {
            int col = n0 + wn * 32 + nf * 8 + 2 * (l & 3);
#pragma unroll
            for (int half_ = 0; half_ < 2; half_++) {
                int r = r_lo + half_ * 8;
                if (r >= ne) continue;
                float gv0 = cg[mf][nf][half_ * 2 + 0], gv1 = cg[mf][nf][half_ * 2 + 1];
                float uv0 = cu[mf][nf][half_ * 2 + 0], uv1 = cu[mf][nf][half_ * 2 + 1];
                float h0 = uv0 * gv0 / (1.0f + expf(-gv0));
                float h1 = uv1 * gv1 / (1.0f + expf(-gv1));
                __half ph[2] = {__float2half_rn(h0), __float2half_rn(h1)};
                *reinterpret_cast<uint32_t*>(hh + (size_t)r * IDIM + col) =
                    *reinterpret_cast<uint32_t*>(ph);
            }
        }
    }
}

// =======================================================================
// down: Y = H*Wd^T; out[token] += w * Y
// CTA 128(M) x 128(N of DIM), Kc=64 over K=2048; cp.async depth-2
// =======================================================================
__global__ __launch_bounds__(256)
void down_mma_kernel(float* __restrict__ out) {
    extern __shared__ char dsm[];

    int e = blockIdx.z, m0 = blockIdx.x * 128, n0 = blockIdx.y * 128;
    int ne = g_count[e];
    if (m0 >= ne) return;
    int tid = threadIdx.x, wid = tid >> 5, l = tid & 31;
    int wm = wid & 3, wn = wid >> 2;

    const __half* AH = g_hh + (size_t)e * ESTRIDE * IDIM;
    const __half* B  = g_wd + (size_t)e * DIM * IDIM;

    uint32_t sb = smem_u32(dsm);

    int lrow = tid >> 3, lch = tid & 7;

    int lar = (l & 7) + 8 * ((l >> 3) & 1);
    int lac = 8 * (l >> 4);
    int lbr = (l & 7) + 8 * (l >> 4);
    int lbc = 8 * ((l >> 3) & 1);

    float c[2][8][4];
#pragma unroll
    for (int i = 0; i < 2; i++)
#pragma unroll
        for (int j = 0; j < 8; j++)
#pragma unroll
            for (int q = 0; q < 4; q++) c[i][j][q] = 0.f;

    const int NK = IDIM / 64;

    auto load_stage = [&](int kc, int s) {
        uint32_t st = sb + s * D_STAGE;
        int k0 = kc * 64;
#pragma unroll
        for (int it = 0; it < 4; it++) {
            int row = lrow + it * 32;
            uint32_t so = row * RBYTES + lch * 16;
            uint32_t sz = (m0 + row < ne) ? 16u : 0u;
            size_t ga = (m0 + row < ne) ? ((size_t)(m0 + row) * IDIM + k0 + lch * 8) : 0;
            CPA16(st + D_A + so, AH + ga, sz);
            size_t gb = (size_t)(n0 + row) * IDIM + k0 + lch * 8;
            CPA16(st + D_B + so, B + gb, 16u);
        }
        CP_COMMIT();
    };

    load_stage(0, 0);

    for (int kc = 0; kc < NK; kc++) {
        if (kc + 1 < NK) { load_stage(kc + 1, (kc + 1) & 1); CP_WAIT(1); }
        else             { CP_WAIT(0); }
        __syncthreads();

        uint32_t st = sb + (kc & 1) * D_STAGE;
#pragma unroll
        for (int ks = 0; ks < 4; ks++) {
            int kkb = ks * 32;
            uint32_t ah[2][4];
#pragma unroll
            for (int mf = 0; mf < 2; mf++) {
                uint32_t off = (uint32_t)((wm * 32 + mf * 16 + lar) * RBYTES + kkb + lac * 2);
                LDSM4(ah[mf][0], ah[mf][1], ah[mf][2], ah[mf][3], st + D_A + off);
            }
#pragma unroll
            for (int p = 0; p < 4; p++) {
                uint32_t off = (uint32_t)((wn * 64 + p * 16 + lbr) * RBYTES + kkb + lbc * 2);
                uint32_t bh[2][2];
                LDSM4(bh[0][0], bh[0][1], bh[1][0], bh[1][1], st + D_B + off);
#pragma unroll
                for (int mf = 0; mf < 2; mf++)
#pragma unroll
                    for (int q = 0; q < 2; q++)
                        MMA16816(c[mf][2 * p + q], ah[mf], bh[q]);
            }
        }
        __syncthreads();
    }

#pragma unroll
    for (int mf = 0; mf < 2; mf++) {
        int r_lo = m0 + wm * 32 + mf * 16 + (l >> 2);
#pragma unroll
        for (int half_ = 0; half_ < 2; half_++) {
            int r = r_lo + half_ * 8;
            if (r >= ne) continue;
            int   t = g_rows[e * ESTRIDE + r];
            float w = g_w[e * ESTRIDE + r];
            float* op = out + (size_t)t * DIM;
#pragma unroll
            for (int nf = 0; nf < 8; nf++) {
                int col = n0 + wn * 64 + nf * 8 + 2 * (l & 3);
                atomicAdd(op + col,     w * c[mf][nf][half_ * 2 + 0]);
                atomicAdd(op + col + 1, w * c[mf][nf][half_ * 2 + 1]);
            }
        }
    }
}

// ---------------- launcher ----------------
extern "C" void kernel_launch(void* const* d_in, const int* in_sizes, int n_in,
                              void* d_out, int out_size) {
    const float* hs = (const float*)d_in[0];
    const float* Wc = (const float*)d_in[1];
    const float* bc = (const float*)d_in[2];
    const float* Wg = (const float*)d_in[3];
    const float* Wu = (const float*)d_in[4];
    const float* Wd = (const float*)d_in[5];
    float* out = (float*)d_out;

    cudaFuncSetAttribute(up_mma_kernel, cudaFuncAttributeMaxDynamicSharedMemorySize, U_SMEM);
    cudaFuncSetAttribute(down_mma_kernel, cudaFuncAttributeMaxDynamicSharedMemorySize, D_SMEM);

    // zero routing counters before the fused prologue's route section
    void* cnt;
    cudaGetSymbolAddress(&cnt, g_count);
    cudaMemsetAsync(cnt, 0, NE * sizeof(int));

    prologue_kernel<<<NB_TOTAL, 256>>>(hs, Wc, bc, Wg, Wu, Wd, out, out_size);

    up_mma_kernel<<<dim3(NTOK / 128, IDIM / 64, NE), 256, U_SMEM>>>();
    down_mma_kernel<<<dim3(NTOK / 128, DIM / 128, NE), 256, D_SMEM>>>(out);
}

// round 10
// speedup vs baseline: 1.2663x; 1.1098x over previous
#include <cuda_runtime.h>
#include <cuda_fp16.h>
#include <math.h>
#include <stdint.h>

#define NE 8
#define DIM 1024
#define IDIM 2048
#define NTOK 4096
#define ESTRIDE 4096

// ---------------- device scratch ----------------
__device__ int   g_count[NE];
__device__ int   g_rows[NE * ESTRIDE];
__device__ float g_w[NE * ESTRIDE];
__device__ __half g_xh[NTOK * DIM];
__device__ __half g_wg[NE * IDIM * DIM];   // [e][i][d] K-major (K=d)
__device__ __half g_wu[NE * IDIM * DIM];
__device__ __half g_wd[NE * DIM * IDIM];   // [e][d][i] K-major (K=i)
__device__ __half g_hh[(size_t)NE * ESTRIDE * IDIM];

// ---------------- helpers ----------------
__device__ __forceinline__ uint32_t smem_u32(const void* p) {
    uint32_t a;
    asm("{ .reg .u64 t; cvta.to.shared.u64 t, %1; cvt.u32.u64 %0, t; }"
        : "=r"(a) : "l"(p));
    return a;
}

#define LDSM4(r0, r1, r2, r3, addr)                                          \
    asm volatile("ldmatrix.sync.aligned.m8n8.x4.shared.b16 {%0,%1,%2,%3}, [%4];" \
                 : "=r"(r0), "=r"(r1), "=r"(r2), "=r"(r3) : "r"(addr))

#define MMA16816(c, a, b)                                                    \
    asm volatile("mma.sync.aligned.m16n8k16.row.col.f32.f16.f16.f32 "        \
                 "{%0,%1,%2,%3},{%4,%5,%6,%7},{%8,%9},{%0,%1,%2,%3};"        \
                 : "+f"((c)[0]), "+f"((c)[1]), "+f"((c)[2]), "+f"((c)[3])    \
                 : "r"((a)[0]), "r"((a)[1]), "r"((a)[2]), "r"((a)[3]),       \
                   "r"((b)[0]), "r"((b)[1]))

#define CPA16(dst, src, sz)                                                  \
    asm volatile("cp.async.cg.shared.global [%0], [%1], 16, %2;"             \
                 :: "r"(dst), "l"(src), "r"(sz) : "memory")
#define CP_COMMIT() asm volatile("cp.async.commit_group;" ::: "memory")
#define CP_WAIT(n)  asm volatile("cp.async.wait_group %0;" ::"n"(n) : "memory")

#define REDV2(ptr, a, b)                                                     \
    asm volatile("red.global.add.v2.f32 [%0], {%1, %2};"                     \
                 :: "l"(ptr), "f"(a), "f"(b) : "memory")

// swizzled byte offset within a tile: 128B rows, 8 x 16B chunks
__device__ __forceinline__ uint32_t SWZ(uint32_t row, uint32_t ch) {
    return row * 128 + ((ch ^ (row & 7)) << 4);
}

// =======================================================================
// fused prologue: [transpose wg | wu | wd | conv_x | route | zero out]
// =======================================================================
#define NB_T    8192
#define NB_CONV 1024
#define NB_ROUTE 512
#define NB_ZERO 512
#define NB_TOTAL (3 * NB_T + NB_CONV + NB_ROUTE + NB_ZERO)

__device__ __forceinline__ void do_transpose(const float* in, __half* oh,
                                             int R, int C, int t, int tid,
                                             float (*sm)[65]) {
    int tilesX = C / 32, tilesY = R / 64;
    int per_e = tilesX * tilesY;
    int e = t / per_e, rem = t - e * per_e;
    int bx = rem % tilesX, by = rem / tilesX;
    const float* ine = in + (size_t)e * R * C;
    int c0 = bx * 32, r0 = by * 64;
    int cx = tid & 31, ry = tid >> 5;
#pragma unroll
    for (int i = 0; i < 64; i += 8)
        sm[cx][ry + i] = ine[(size_t)(r0 + ry + i) * C + c0 + cx];
    __syncthreads();
    __half* ohe = oh + (size_t)e * R * C;
    int rx = tid & 63, cy = tid >> 6;
#pragma unroll
    for (int j = 0; j < 32; j += 4)
        ohe[(size_t)(c0 + cy + j) * R + r0 + rx] = __float2half_rn(sm[cy + j][rx]);
}

__device__ __forceinline__ void do_route(const float* x, const float* Wc,
                                         const float* bc, int rb, int tid) {
    int gwarp = (rb * 256 + tid) >> 5;
    int lane = tid & 31;
    const float* xr = x + (size_t)gwarp * DIM;
    float acc[NE];
#pragma unroll
    for (int e = 0; e < NE; e++) acc[e] = 0.0f;
    for (int d = lane; d < DIM; d += 32) {
        float xv = xr[d];
#pragma unroll
        for (int e = 0; e < NE; e++) acc[e] += xv * Wc[e * DIM + d];
    }
#pragma unroll
    for (int e = 0; e < NE; e++)
#pragma unroll
        for (int off = 16; off > 0; off >>= 1)
            acc[e] += __shfl_xor_sync(0xffffffffu, acc[e], off);
    if (lane == 0) {
        float conf[NE];
#pragma unroll
        for (int e = 0; e < NE; e++)
            conf[e] = 1.0f / (1.0f + expf(-(acc[e] + bc[e])));
        int i0 = 0;
#pragma unroll
        for (int e = 1; e < NE; e++) if (conf[e] > conf[i0]) i0 = e;
        int i1 = -1;
#pragma unroll
        for (int e = 0; e < NE; e++) {
            if (e == i0) continue;
            if (i1 < 0 || conf[e] > conf[i1]) i1 = e;
        }
        float v0 = conf[i0], v1 = conf[i1];
        float w0 = 1.0f / (1.0f + expf(v1 - v0));
        float w1 = 1.0f / (1.0f + expf(v0 - v1));
        int p0 = atomicAdd(&g_count[i0], 1);
        g_rows[i0 * ESTRIDE + p0] = gwarp;
        g_w[i0 * ESTRIDE + p0] = w0;
        int p1 = atomicAdd(&g_count[i1], 1);
        g_rows[i1 * ESTRIDE + p1] = gwarp;
        g_w[i1 * ESTRIDE + p1] = w1;
    }
}

__global__ __launch_bounds__(256)
void prologue_kernel(const float* __restrict__ hs,
                     const float* __restrict__ Wc,
                     const float* __restrict__ bc,
                     const float* __restrict__ Wg,
                     const float* __restrict__ Wu,
                     const float* __restrict__ Wd,
                     float* __restrict__ out, int out_n) {
    __shared__ float sm[32][65];
    int b = blockIdx.x, tid = threadIdx.x;
    if (b < NB_T) {
        do_transpose(Wg, g_wg, DIM, IDIM, b, tid, sm);
    } else if (b < 2 * NB_T) {
        do_transpose(Wu, g_wu, DIM, IDIM, b - NB_T, tid, sm);
    } else if (b < 3 * NB_T) {
        do_transpose(Wd, g_wd, IDIM, DIM, b - 2 * NB_T, tid, sm);
    } else if (b < 3 * NB_T + NB_CONV) {
        int cb = b - 3 * NB_T;
        const int N4 = NTOK * DIM / 4;
        for (int j = cb * 256 + tid; j < N4; j += NB_CONV * 256) {
            float4 v = reinterpret_cast<const float4*>(hs)[j];
            __half hv[4] = {__float2half_rn(v.x), __float2half_rn(v.y),
                            __float2half_rn(v.z), __float2half_rn(v.w)};
            reinterpret_cast<uint2*>(g_xh)[j] = *reinterpret_cast<uint2*>(hv);
        }
    } else if (b < 3 * NB_T + NB_CONV + NB_ROUTE) {
        do_route(hs, Wc, bc, b - 3 * NB_T - NB_CONV, tid);
    } else {
        int zb = b - 3 * NB_T - NB_CONV - NB_ROUTE;
        int n4 = out_n / 4;
        float4 z = make_float4(0.f, 0.f, 0.f, 0.f);
        for (int j = zb * 256 + tid; j < n4; j += NB_ZERO * 256)
            reinterpret_cast<float4*>(out)[j] = z;
    }
}

// =======================================================================
// Tiling: Kc=64, XOR-swizzled 128B smem rows, depth-3 cp.async pipeline.
// =======================================================================
#define U_A   0                     // 128*128 = 16384
#define U_BG  16384                 // 64*128 = 8192
#define U_BU  24576
#define U_STAGE 32768
#define U_SMEM (3 * U_STAGE)        // 98304

#define D_A   0                     // 128*128
#define D_B   16384                 // 128*128
#define D_STAGE 32768
#define D_SMEM (3 * D_STAGE)        // 98304

// =======================================================================
// up: g = X*Wg^T, u = X*Wu^T (fp16, fp32 accum); h = silu(g)*u -> fp16
// CTA 128(M) x 64(N of IDIM), Kc=64
// =======================================================================
__global__ __launch_bounds__(256)
void up_mma_kernel() {
    extern __shared__ char dsm[];
    __shared__ int stok[128];

    int e = blockIdx.z, m0 = blockIdx.x * 128, n0 = blockIdx.y * 64;
    int ne = g_count[e];
    if (m0 >= ne) return;
    int tid = threadIdx.x, wid = tid >> 5, l = tid & 31;
    if (tid < 128) stok[tid] = (m0 + tid < ne) ? g_rows[e * ESTRIDE + m0 + tid] : -1;
    __syncthreads();

    int wm = wid & 3, wn = wid >> 2;

    const __half* WG = g_wg + (size_t)e * IDIM * DIM;
    const __half* WU = g_wu + (size_t)e * IDIM * DIM;

    uint32_t sb = smem_u32(dsm);

    int lrow = tid >> 3, lch = tid & 7;

    int lar = (l & 7) + 8 * ((l >> 3) & 1);
    int la_ch = l >> 4;            // chunk sub-index for A
    int lbr = (l & 7) + 8 * (l >> 4);
    int lb_ch = (l >> 3) & 1;      // chunk sub-index for B

    float cg[2][4][4], cu[2][4][4];
#pragma unroll
    for (int i = 0; i < 2; i++)
#pragma unroll
        for (int j = 0; j < 4; j++)
#pragma unroll
            for (int q = 0; q < 4; q++) { cg[i][j][q] = 0.f; cu[i][j][q] = 0.f; }

    const int NK = DIM / 64;

    auto load_stage = [&](int kc, int s) {
        uint32_t st = sb + s * U_STAGE;
        int k0 = kc * 64;
#pragma unroll
        for (int it = 0; it < 4; it++) {
            int row = lrow + it * 32;
            int tok = stok[row];
            uint32_t sz = (tok >= 0) ? 16u : 0u;
            size_t go = (tok >= 0) ? ((size_t)tok * DIM + k0 + lch * 8) : 0;
            CPA16(st + U_A + SWZ(row, lch), g_xh + go, sz);
        }
#pragma unroll
        for (int it = 0; it < 2; it++) {
            int row = lrow + it * 32;
            size_t go = (size_t)(n0 + row) * DIM + k0 + lch * 8;
            uint32_t so = SWZ(row, lch);
            CPA16(st + U_BG + so, WG + go, 16u);
            CPA16(st + U_BU + so, WU + go, 16u);
        }
        CP_COMMIT();
    };

    load_stage(0, 0);
    load_stage(1, 1);

    int s_cur = 0;
    for (int kc = 0; kc < NK; kc++) {
        if (kc + 2 < NK) {
            int s2 = s_cur + 2; if (s2 >= 3) s2 -= 3;
            load_stage(kc + 2, s2);
            CP_WAIT(2);
        } else if (kc + 1 < NK) {
            CP_WAIT(1);
        } else {
            CP_WAIT(0);
        }
        __syncthreads();

        uint32_t st = sb + s_cur * U_STAGE;
#pragma unroll
        for (int ks = 0; ks < 4; ks++) {
            uint32_t ah[2][4];
#pragma unroll
            for (int mf = 0; mf < 2; mf++) {
                uint32_t row = wm * 32 + mf * 16 + lar;
                LDSM4(ah[mf][0], ah[mf][1], ah[mf][2], ah[mf][3],
                      st + U_A + SWZ(row, 2 * ks + la_ch));
            }
#pragma unroll
            for (int p = 0; p < 2; p++) {
                uint32_t row = wn * 32 + p * 16 + lbr;
                uint32_t off = SWZ(row, 2 * ks + lb_ch);
                uint32_t bg[2][2], bu[2][2];
                LDSM4(bg[0][0], bg[0][1], bg[1][0], bg[1][1], st + U_BG + off);
                LDSM4(bu[0][0], bu[0][1], bu[1][0], bu[1][1], st + U_BU + off);
#pragma unroll
                for (int mf = 0; mf < 2; mf++)
#pragma unroll
                    for (int q = 0; q < 2; q++) {
                        int nf = 2 * p + q;
                        MMA16816(cg[mf][nf], ah[mf], bg[q]);
                        MMA16816(cu[mf][nf], ah[mf], bu[q]);
                    }
            }
        }
        __syncthreads();
        if (++s_cur == 3) s_cur = 0;
    }

    __half* hh = g_hh + (size_t)e * ESTRIDE * IDIM;
#pragma unroll
    for (int mf = 0; mf < 2; mf++) {
        int r_lo = m0 + wm * 32 + mf * 16 + (l >> 2);
#pragma unroll
        for (int nf = 0; nf < 4; nf++) {
            int col = n0 + wn * 32 + nf * 8 + 2 * (l & 3);
#pragma unroll
            for (int half_ = 0; half_ < 2; half_++) {
                int r = r_lo + half_ * 8;
                if (r >= ne) continue;
                float gv0 = cg[mf][nf][half_ * 2 + 0], gv1 = cg[mf][nf][half_ * 2 + 1];
                float uv0 = cu[mf][nf][half_ * 2 + 0], uv1 = cu[mf][nf][half_ * 2 + 1];
                float h0 = uv0 * gv0 / (1.0f + expf(-gv0));
                float h1 = uv1 * gv1 / (1.0f + expf(-gv1));
                __half ph[2] = {__float2half_rn(h0), __float2half_rn(h1)};
                *reinterpret_cast<uint32_t*>(hh + (size_t)r * IDIM + col) =
                    *reinterpret_cast<uint32_t*>(ph);
            }
        }
    }
}

// =======================================================================
// down: Y = H*Wd^T; out[token] += w * Y  (vector red.add.v2.f32)
// CTA 128(M) x 128(N of DIM), Kc=64 over K=2048
// =======================================================================
__global__ __launch_bounds__(256)
void down_mma_kernel(float* __restrict__ out) {
    extern __shared__ char dsm[];

    int e = blockIdx.z, m0 = blockIdx.x * 128, n0 = blockIdx.y * 128;
    int ne = g_count[e];
    if (m0 >= ne) return;
    int tid = threadIdx.x, wid = tid >> 5, l = tid & 31;
    int wm = wid & 3, wn = wid >> 2;

    const __half* AH = g_hh + (size_t)e * ESTRIDE * IDIM;
    const __half* B  = g_wd + (size_t)e * DIM * IDIM;

    uint32_t sb = smem_u32(dsm);

    int lrow = tid >> 3, lch = tid & 7;

    int lar = (l & 7) + 8 * ((l >> 3) & 1);
    int la_ch = l >> 4;
    int lbr = (l & 7) + 8 * (l >> 4);
    int lb_ch = (l >> 3) & 1;

    float c[2][8][4];
#pragma unroll
    for (int i = 0; i < 2; i++)
#pragma unroll
        for (int j = 0; j < 8; j++)
#pragma unroll
            for (int q = 0; q < 4; q++) c[i][j][q] = 0.f;

    const int NK = IDIM / 64;

    auto load_stage = [&](int kc, int s) {
        uint32_t st = sb + s * D_STAGE;
        int k0 = kc * 64;
#pragma unroll
        for (int it = 0; it < 4; it++) {
            int row = lrow + it * 32;
            uint32_t so = SWZ(row, lch);
            uint32_t sz = (m0 + row < ne) ? 16u : 0u;
            size_t ga = (m0 + row < ne) ? ((size_t)(m0 + row) * IDIM + k0 + lch * 8) : 0;
            CPA16(st + D_A + so, AH + ga, sz);
            size_t gb = (size_t)(n0 + row) * IDIM + k0 + lch * 8;
            CPA16(st + D_B + so, B + gb, 16u);
        }
        CP_COMMIT();
    };

    load_stage(0, 0);
    load_stage(1, 1);

    int s_cur = 0;
    for (int kc = 0; kc < NK; kc++) {
        if (kc + 2 < NK) {
            int s2 = s_cur + 2; if (s2 >= 3) s2 -= 3;
            load_stage(kc + 2, s2);
            CP_WAIT(2);
        } else if (kc + 1 < NK) {
            CP_WAIT(1);
        } else {
            CP_WAIT(0);
        }
        __syncthreads();

        uint32_t st = sb + s_cur * D_STAGE;
#pragma unroll
        for (int ks = 0; ks < 4; ks++) {
            uint32_t ah[2][4];
#pragma unroll
            for (int mf = 0; mf < 2; mf++) {
                uint32_t row = wm * 32 + mf * 16 + lar;
                LDSM4(ah[mf][0], ah[mf][1], ah[mf][2], ah[mf][3],
                      st + D_A + SWZ(row, 2 * ks + la_ch));
            }
#pragma unroll
            for (int p = 0; p < 4; p++) {
                uint32_t row = wn * 64 + p * 16 + lbr;
                uint32_t off = SWZ(row, 2 * ks + lb_ch);
                uint32_t bh[2][2];
                LDSM4(bh[0][0], bh[0][1], bh[1][0], bh[1][1], st + D_B + off);
#pragma unroll
                for (int mf = 0; mf < 2; mf++)
#pragma unroll
                    for (int q = 0; q < 2; q++)
                        MMA16816(c[mf][2 * p + q], ah[mf], bh[q]);
            }
        }
        __syncthreads();
        if (++s_cur == 3) s_cur = 0;
    }

#pragma unroll
    for (int mf = 0; mf < 2; mf++) {
        int r_lo = m0 + wm * 32 + mf * 16 + (l >> 2);
#pragma unroll
        for (int half_ = 0; half_ < 2; half_++) {
            int r = r_lo + half_ * 8;
            if (r >= ne) continue;
            int   t = g_rows[e * ESTRIDE + r];
            float w = g_w[e * ESTRIDE + r];
            float* op = out + (size_t)t * DIM;
#pragma unroll
            for (int nf = 0; nf < 8; nf++) {
                int col = n0 + wn * 64 + nf * 8 + 2 * (l & 3);
                REDV2(op + col, w * c[mf][nf][half_ * 2 + 0],
                                w * c[mf][nf][half_ * 2 + 1]);
            }
        }
    }
}

// ---------------- launcher ----------------
extern "C" void kernel_launch(void* const* d_in, const int* in_sizes, int n_in,
                              void* d_out, int out_size) {
    const float* hs = (const float*)d_in[0];
    const float* Wc = (const float*)d_in[1];
    const float* bc = (const float*)d_in[2];
    const float* Wg = (const float*)d_in[3];
    const float* Wu = (const float*)d_in[4];
    const float* Wd = (const float*)d_in[5];
    float* out = (float*)d_out;

    cudaFuncSetAttribute(up_mma_kernel, cudaFuncAttributeMaxDynamicSharedMemorySize, U_SMEM);
    cudaFuncSetAttribute(down_mma_kernel, cudaFuncAttributeMaxDynamicSharedMemorySize, D_SMEM);

    void* cnt;
    cudaGetSymbolAddress(&cnt, g_count);
    cudaMemsetAsync(cnt, 0, NE * sizeof(int));

    prologue_kernel<<<NB_TOTAL, 256>>>(hs, Wc, bc, Wg, Wu, Wd, out, out_size);

    up_mma_kernel<<<dim3(NTOK / 128, IDIM / 64, NE), 256, U_SMEM>>>();
    down_mma_kernel<<<dim3(NTOK / 128, DIM / 128, NE), 256, D_SMEM>>>(out);
}